// round 3
// baseline (speedup 1.0000x reference)
#include <cuda_runtime.h>
#include <cuda_bf16.h>
#include <math.h>

// Problem dims
#define TT 512
#define BB 64
#define EE 512
#define HD 512
#define HH 1024
#define CC 16
#define START_TAG 14
#define STOP_TAG 15
#define NG 4096          // 2 dirs * 4 gates * HD
#define MROWS (TT*BB)    // 32768

// ---------------- scratch (device globals; no runtime allocation) ------------
__device__ float g_X0[(size_t)MROWS * EE];          //  64 MB
__device__ float g_G [(size_t)MROWS * NG];          // 512 MB (reused L0/L1)
__device__ float g_H0[(size_t)MROWS * HH];          // 128 MB
__device__ float g_H1[(size_t)MROWS * HH];          // 128 MB
__device__ float g_feats[(size_t)BB * TT * CC];
__device__ float g_hbuf[2 * 2 * BB * HD];           // [parity][dir][B][HD]

// grid barrier state (device globals are zero-initialized; count always
// returns to 0 at the end of each barrier, gen increments monotonically
// and wraps — safe across graph replays)
__device__ unsigned int g_bar_count;
__device__ unsigned int g_bar_gen;

__device__ __forceinline__ void grid_barrier(int nblk) {
    __syncthreads();
    if (threadIdx.x == 0) {
        __threadfence();                       // release all prior writes
        unsigned int gen = *(volatile unsigned int*)&g_bar_gen;
        if (atomicAdd(&g_bar_count, 1u) == (unsigned)(nblk - 1)) {
            g_bar_count = 0;
            __threadfence();
            atomicAdd(&g_bar_gen, 1u);         // release the new generation
        } else {
            unsigned int cur;
            do {
                asm volatile("ld.acquire.gpu.u32 %0, [%1];"
                             : "=r"(cur) : "l"(&g_bar_gen));
            } while (cur == gen);
        }
    }
    __syncthreads();
}

// ---------------- embedding gather: X0[t*B+b][:] = emb[sent[b][t]] -----------
__global__ void embed_kernel(const int* __restrict__ sent,
                             const float* __restrict__ emb,
                             float* __restrict__ X0) {
    int m = blockIdx.x;          // t*B + b
    int t = m >> 6;
    int b = m & 63;
    int tok = sent[b * TT + t];
    const float4* src = reinterpret_cast<const float4*>(emb + (size_t)tok * EE);
    float4* dst = reinterpret_cast<float4*>(X0 + (size_t)m * EE);
    dst[threadIdx.x] = src[threadIdx.x];   // 128 threads * float4 = 512 floats
}

// ---------------- fp32 SGEMM: C[M][N] = A[M][K] * W[N][K]^T + b1[n] + b2[n] --
// BM=128, BN=128, BK=8, 256 threads, 8x8 per thread
__global__ __launch_bounds__(256, 2)
void sgemm_bias(const float* __restrict__ A,
                const float* __restrict__ W,
                const float* __restrict__ b1,
                const float* __restrict__ b2,
                float* __restrict__ C,
                int M, int N, int K) {
    __shared__ float As[8][132];
    __shared__ float Bs[8][132];

    const int tid = threadIdx.x;
    const int n0 = blockIdx.x * 128;
    const int m0 = blockIdx.y * 128;
    const int tx = tid & 15;
    const int ty = tid >> 4;

    const int lr = tid >> 1;          // 0..127 : row within tile
    const int lk = (tid & 1) * 4;     // 0 or 4 : k-offset within 8

    float acc[8][8];
#pragma unroll
    for (int i = 0; i < 8; i++)
#pragma unroll
        for (int j = 0; j < 8; j++) acc[i][j] = 0.f;

    const float* Arow = A + (size_t)(m0 + lr) * K + lk;
    const float* Wrow = W + (size_t)(n0 + lr) * K + lk;

    for (int kt = 0; kt < K; kt += 8) {
        float4 av = *reinterpret_cast<const float4*>(Arow + kt);
        float4 wv = *reinterpret_cast<const float4*>(Wrow + kt);
        As[lk + 0][lr] = av.x; As[lk + 1][lr] = av.y;
        As[lk + 2][lr] = av.z; As[lk + 3][lr] = av.w;
        Bs[lk + 0][lr] = wv.x; Bs[lk + 1][lr] = wv.y;
        Bs[lk + 2][lr] = wv.z; Bs[lk + 3][lr] = wv.w;
        __syncthreads();
#pragma unroll
        for (int k = 0; k < 8; k++) {
            float4 a0 = *reinterpret_cast<const float4*>(&As[k][ty * 8]);
            float4 a1 = *reinterpret_cast<const float4*>(&As[k][ty * 8 + 4]);
            float4 c0 = *reinterpret_cast<const float4*>(&Bs[k][tx * 8]);
            float4 c1 = *reinterpret_cast<const float4*>(&Bs[k][tx * 8 + 4]);
            float ar[8] = {a0.x, a0.y, a0.z, a0.w, a1.x, a1.y, a1.z, a1.w};
            float br[8] = {c0.x, c0.y, c0.z, c0.w, c1.x, c1.y, c1.z, c1.w};
#pragma unroll
            for (int i = 0; i < 8; i++)
#pragma unroll
                for (int j = 0; j < 8; j++) acc[i][j] += ar[i] * br[j];
        }
        __syncthreads();
    }

#pragma unroll
    for (int i = 0; i < 8; i++) {
        int row = m0 + ty * 8 + i;
        float* crow = C + (size_t)row * N + n0 + tx * 8;
        const float* p1 = b1 + n0 + tx * 8;
        const float* p2 = b2 + n0 + tx * 8;
#pragma unroll
        for (int j = 0; j < 8; j++)
            crow[j] = acc[i][j] + p1[j] + p2[j];
    }
}

// ---------------- persistent bidirectional LSTM layer ------------------------
// grid (64, 2): x = 8-hidden-unit tile, y = direction. 128 threads.
// Loops over all T=512 steps with a grid barrier between steps.
// Per step: tile 64 batch x 32 gate-cols (4 gates x 8 units), K=HD reduction.
// Cell state c lives in registers (block exclusively owns its (dir,u) slice).
__global__ __launch_bounds__(128)
void lstm_layer(const float* __restrict__ G,    // [MROWS][NG]
                const float* __restrict__ Whh,  // [2][2048][HD]
                const float* __restrict__ h0,   // [2][B][HD] (this layer)
                const float* __restrict__ c0,   // [2][B][HD] (this layer)
                float* __restrict__ hbuf,       // [2][2][B][HD]
                float* __restrict__ Hcat) {     // [T][B][HH]
    const int dir = blockIdx.y;
    const int u0 = blockIdx.x * 8;
    const int tid = threadIdx.x;
    const float* W = Whh + (size_t)dir * 2048 * HD;

    __shared__ float Hs[16][68];
    __shared__ float Ws[16][36];
    __shared__ float gs[4][64][8];

    // ---- init: c -> registers, h0 -> parity-0 buffer ----
    float cr[4];
#pragma unroll
    for (int i = 0; i < 4; i++) {
        int p = tid + i * 128;           // 0..511
        int b = p >> 3, ul = p & 7;
        size_t idx = (size_t)dir * BB * HD + b * HD + u0 + ul;
        cr[i] = c0[idx];
        hbuf[idx] = h0[idx];             // parity 0
    }
    grid_barrier(128);

    const int b0  = (tid >> 3) * 4;   // batch group (0..60 step 4)
    const int cg0 = (tid & 7) * 4;    // gate-col group (0..28 step 4)

    // W/h load mappings
    const int lcc = tid & 31;               // 0..31 gate-col
    const int lgate = lcc >> 3;
    const int lu = u0 + (lcc & 7);
    const int lkq = tid >> 5;               // 0..3
    const int lb = tid & 63;                // h-load batch
    const int hkq0 = tid >> 6;              // 0..1

    for (int s = 0; s < TT; s++) {
        const int t = dir ? (TT - 1 - s) : s;
        const float* h = hbuf + (size_t)(s & 1) * 2 * BB * HD
                              + (size_t)dir * BB * HD;
        float* ho = hbuf + (size_t)((s + 1) & 1) * 2 * BB * HD
                         + (size_t)dir * BB * HD;

        float acc[4][4];
#pragma unroll
        for (int i = 0; i < 4; i++)
#pragma unroll
            for (int j = 0; j < 4; j++) acc[i][j] = 0.f;

        for (int kt = 0; kt < HD; kt += 16) {
            // h tile: 64 x 16
#pragma unroll
            for (int it = 0; it < 2; it++) {
                int kq = hkq0 + it * 2;
                float4 v = *reinterpret_cast<const float4*>(&h[lb * HD + kt + kq * 4]);
                Hs[kq * 4 + 0][lb] = v.x; Hs[kq * 4 + 1][lb] = v.y;
                Hs[kq * 4 + 2][lb] = v.z; Hs[kq * 4 + 3][lb] = v.w;
            }
            // W tile: 32 x 16
            {
                float4 v = *reinterpret_cast<const float4*>(
                    &W[(size_t)(lgate * HD + lu) * HD + kt + lkq * 4]);
                Ws[lkq * 4 + 0][lcc] = v.x; Ws[lkq * 4 + 1][lcc] = v.y;
                Ws[lkq * 4 + 2][lcc] = v.z; Ws[lkq * 4 + 3][lcc] = v.w;
            }
            __syncthreads();
#pragma unroll
            for (int k = 0; k < 16; k++) {
                float4 hv = *reinterpret_cast<const float4*>(&Hs[k][b0]);
                float4 wv = *reinterpret_cast<const float4*>(&Ws[k][cg0]);
                float ar[4] = {hv.x, hv.y, hv.z, hv.w};
                float br[4] = {wv.x, wv.y, wv.z, wv.w};
#pragma unroll
                for (int i = 0; i < 4; i++)
#pragma unroll
                    for (int j = 0; j < 4; j++) acc[i][j] += ar[i] * br[j];
            }
            __syncthreads();
        }

        // add precomputed input gates + biases, stage in smem grouped by gate
        const int row0 = t * BB;
#pragma unroll
        for (int i = 0; i < 4; i++) {
            int b = b0 + i;
#pragma unroll
            for (int j = 0; j < 4; j++) {
                int cc = cg0 + j;
                int gate = cc >> 3;
                int ul = cc & 7;
                float v = acc[i][j] +
                    G[(size_t)(row0 + b) * NG + dir * 2048 + gate * HD + u0 + ul];
                gs[gate][b][ul] = v;
            }
        }
        __syncthreads();

        // LSTM cell for the 64x8 (batch, unit) pairs of this tile
#pragma unroll
        for (int i = 0; i < 4; i++) {
            int p = tid + i * 128;
            int b = p >> 3;
            int ul = p & 7;
            int u = u0 + ul;
            float ig = gs[0][b][ul];
            float fg = gs[1][b][ul];
            float gg = gs[2][b][ul];
            float og = gs[3][b][ul];
            float si = 1.f / (1.f + expf(-ig));
            float sf = 1.f / (1.f + expf(-fg));
            float so = 1.f / (1.f + expf(-og));
            float cn = sf * cr[i] + si * tanhf(gg);
            float hn = so * tanhf(cn);
            cr[i] = cn;
            ho[b * HD + u] = hn;
            Hcat[(size_t)t * BB * HH + b * HH + dir * HD + u] = hn;
        }
        grid_barrier(128);
    }
}

// ---------------- final linear: feats[b][t][c] = H1[t*B+b] . lin_w[c] + lin_b -
__global__ void linear_feats(const float* __restrict__ H1,
                             const float* __restrict__ lw,
                             const float* __restrict__ lb,
                             float* __restrict__ feats) {
    int warp = (blockIdx.x * blockDim.x + threadIdx.x) >> 5;
    int lane = threadIdx.x & 31;
    if (warp >= MROWS) return;
    const float* hrow = H1 + (size_t)warp * HH;
    float acc[CC];
#pragma unroll
    for (int c = 0; c < CC; c++) acc[c] = 0.f;
    for (int k = lane; k < HH; k += 32) {
        float hv = hrow[k];
#pragma unroll
        for (int c = 0; c < CC; c++) acc[c] += hv * lw[c * HH + k];
    }
#pragma unroll
    for (int c = 0; c < CC; c++) {
        float v = acc[c];
#pragma unroll
        for (int o = 16; o; o >>= 1) v += __shfl_down_sync(0xffffffffu, v, o);
        if (lane == 0) {
            int t = warp >> 6, b = warp & 63;
            feats[((size_t)b * TT + t) * CC + c] = v + lb[c];
        }
    }
}

// ---------------- Viterbi decode: one block (16 threads) per batch -----------
__global__ void viterbi_kernel(const float* __restrict__ feats,
                               const float* __restrict__ trans,
                               float* __restrict__ out,
                               int write_scores, int write_paths, int path_off) {
    const int b = blockIdx.x;
    const int c = threadIdx.x;   // 0..15 = "next" tag
    __shared__ unsigned char bp[TT][CC];

    float tr[CC];
#pragma unroll
    for (int p = 0; p < CC; p++) tr[p] = trans[c * CC + p];

    float fv = (c == START_TAG) ? 0.f : -10000.f;
    const float* f = feats + (size_t)b * TT * CC;

    for (int t = 0; t < TT; t++) {
        float best = -3.4e38f;
        int arg = 0;
#pragma unroll
        for (int p = 0; p < CC; p++) {
            float sc = __shfl_sync(0x0000ffffu, fv, p) + tr[p];
            if (sc > best) { best = sc; arg = p; }   // strict > keeps first index
        }
        bp[t][c] = (unsigned char)arg;
        fv = best + f[t * CC + c];
    }

    float term = fv + trans[STOP_TAG * CC + c];
    float bv = term;
    int bi = c;
#pragma unroll
    for (int o = 8; o; o >>= 1) {
        float ov = __shfl_down_sync(0x0000ffffu, bv, o);
        int oi = __shfl_down_sync(0x0000ffffu, bi, o);
        if (ov > bv || (ov == bv && oi < bi)) { bv = ov; bi = oi; }
    }
    bv = __shfl_sync(0x0000ffffu, bv, 0);
    bi = __shfl_sync(0x0000ffffu, bi, 0);

    if (c == 0) {
        if (write_scores) out[b] = bv;
        if (write_paths) {
            int tag = bi;
            for (int t = TT - 1; t >= 0; t--) {
                out[path_off + b * TT + t] = (float)tag;
                tag = bp[t][tag];
            }
        }
    }
}

// ---------------- launch ------------------------------------------------------
extern "C" void kernel_launch(void* const* d_in, const int* in_sizes, int n_in,
                              void* d_out, int out_size) {
    const int*   sent    = (const int*)  d_in[0];
    const float* emb     = (const float*)d_in[1];
    const float* wih0    = (const float*)d_in[2];   // [2,2048,512]
    const float* whh0    = (const float*)d_in[3];   // [2,2048,512]
    const float* bih0    = (const float*)d_in[4];   // [2,2048]
    const float* bhh0    = (const float*)d_in[5];
    const float* wih1    = (const float*)d_in[6];   // [2,2048,1024]
    const float* whh1    = (const float*)d_in[7];   // [2,2048,512]
    const float* bih1    = (const float*)d_in[8];
    const float* bhh1    = (const float*)d_in[9];
    const float* linw    = (const float*)d_in[10];  // [16,1024]
    const float* linb    = (const float*)d_in[11];  // [16]
    const float* trans   = (const float*)d_in[12];  // [16,16]
    const float* h0      = (const float*)d_in[13];  // [4,B,HD]
    const float* c0      = (const float*)d_in[14];  // [4,B,HD]

    float *pX0, *pG, *pH0, *pH1, *pfe, *phb;
    cudaGetSymbolAddress((void**)&pX0, g_X0);
    cudaGetSymbolAddress((void**)&pG,  g_G);
    cudaGetSymbolAddress((void**)&pH0, g_H0);
    cudaGetSymbolAddress((void**)&pH1, g_H1);
    cudaGetSymbolAddress((void**)&pfe, g_feats);
    cudaGetSymbolAddress((void**)&phb, g_hbuf);

    // 1) embedding gather
    embed_kernel<<<MROWS, 128>>>(sent, emb, pX0);

    // 2) layer-0 input projection (both dirs fused: W viewed as [4096,512])
    sgemm_bias<<<dim3(NG / 128, MROWS / 128), 256>>>(
        pX0, wih0, bih0, bhh0, pG, MROWS, NG, EE);

    // 3) layer-0 recurrence (persistent, 512 steps internal)
    lstm_layer<<<dim3(64, 2), 128>>>(pG, whh0, h0, c0, phb, pH0);

    // 4) layer-1 input projection (K=1024)
    sgemm_bias<<<dim3(NG / 128, MROWS / 128), 256>>>(
        pH0, wih1, bih1, bhh1, pG, MROWS, NG, HH);

    // 5) layer-1 recurrence
    lstm_layer<<<dim3(64, 2), 128>>>(pG, whh1,
                                     h0 + 2 * BB * HD, c0 + 2 * BB * HD,
                                     phb, pH1);

    // 6) linear -> feats
    linear_feats<<<(MROWS * 32 + 255) / 256, 256>>>(pH1, linw, linb, pfe);

    // 7) Viterbi decode + output write
    float* out = (float*)d_out;
    int write_scores, write_paths, path_off;
    if (out_size >= BB + BB * TT) { write_scores = 1; write_paths = 1; path_off = BB; }
    else if (out_size == BB * TT) { write_scores = 0; write_paths = 1; path_off = 0; }
    else                          { write_scores = 1; write_paths = 0; path_off = 0; }
    viterbi_kernel<<<BB, CC>>>(pfe, trans, out, write_scores, write_paths, path_off);
}